// round 2
// baseline (speedup 1.0000x reference)
#include <cuda_runtime.h>
#include <cuda_bf16.h>

#define NN   800
#define CC   64
#define TRS  40
#define SPT  10
#define BUF  120
#define TT   400
#define NBLK 50
#define RPB  16     // rows (warps) per block
#define THREADS 512
#define KPL  25     // 800 / 32 j-values per lane
#define D0CAP 96    // max d==0 entries per row (mean ~6.7, Poisson tail safe)
#define HBYTES (BUF * NN * 2)

// ---------------- scratch (static device allocations; no cudaMalloc) --------
__device__ __align__(16) __nv_bfloat16 g_HT0[BUF * NN];  // transposed hE (bf16)
__device__ __align__(16) float g_XTR[TRS * NN];          // x at last step of each TR
__device__ __align__(16) float g_Xg[2 * NN];             // ping-pong x broadcast
__device__ int   g_ctr[TT];                              // per-step arrival counters
__device__ int   g_go[TT];                               // per-step release flags
__device__ float g_rowsum[NN];                           // sum_j |sc[i,j]|
__device__ float g_rowsq[NN];                            // sum_j sc[i,j]^2
__device__ float g_invnorm;                              // 1/||sc||_F
__device__ int   g_flag64;                               // delays stored as int64?

// ---------------- per-row stats: rowsum(|sc|), rowsq(sc^2) ------------------
__global__ void k_rowstats(const float* __restrict__ sc) {
    int i = blockIdx.x, tid = threadIdx.x;
    float s1 = 0.f, s2 = 0.f;
    for (int j = tid; j < NN; j += 128) {
        float v = sc[i * NN + j];
        s1 += fabsf(v);
        s2 += v * v;
    }
    #pragma unroll
    for (int o = 16; o; o >>= 1) {
        s1 += __shfl_xor_sync(0xffffffffu, s1, o);
        s2 += __shfl_xor_sync(0xffffffffu, s2, o);
    }
    __shared__ float sh1[4], sh2[4];
    if ((tid & 31) == 0) { sh1[tid >> 5] = s1; sh2[tid >> 5] = s2; }
    __syncthreads();
    if (tid == 0) {
        g_rowsum[i] = sh1[0] + sh1[1] + sh1[2] + sh1[3];
        g_rowsq[i]  = sh2[0] + sh2[1] + sh2[2] + sh2[3];
    }
}

// ---------------- norm reduction -------------------------------------------
__global__ void k_norm() {
    int tid = threadIdx.x;
    float s = 0.f;
    for (int i = tid; i < NN; i += 256) s += g_rowsq[i];
    #pragma unroll
    for (int o = 16; o; o >>= 1) s += __shfl_xor_sync(0xffffffffu, s, o);
    __shared__ float sh[8];
    if ((tid & 31) == 0) sh[tid >> 5] = s;
    __syncthreads();
    if (tid == 0) {
        float tot = 0.f;
        #pragma unroll
        for (int w = 0; w < 8; w++) tot += sh[w];
        g_invnorm = rsqrtf(tot);
    }
}

// ---------------- prep: transpose hE -> bf16, zero flags, dtype detect ------
__global__ void k_prep2(const float* __restrict__ hE, const void* __restrict__ delays) {
    int g = blockIdx.x * blockDim.x + threadIdx.x;
    if (g < BUF * NN) {
        int m = g / NN, j = g % NN;
        g_HT0[g] = __float2bfloat16(hE[j * BUF + (BUF - 1 - m)]);
    }
    if (g < TT) { g_ctr[g] = 0; g_go[g] = 0; }
    if (g == 0) {
        const int* p = (const int*)delays;
        int any = 0;
        for (int k = 0; k < 100; k++) any |= p[2 * k + 1];
        g_flag64 = (any == 0) ? 1 : 0;  // int64: high words all zero
    }
}

__device__ __forceinline__ float warp_sum(float v) {
    #pragma unroll
    for (int o = 16; o; o >>= 1) v += __shfl_xor_sync(0xffffffffu, v, o);
    return v;
}

// ---------------- main persistent integration kernel ------------------------
__global__ void __launch_bounds__(THREADS, 1)
k_main(const float* __restrict__ external, const float* __restrict__ hx,
       const float* __restrict__ sc, const float* __restrict__ noise,
       const void* __restrict__ delays) {
    extern __shared__ __align__(16) unsigned char smem_raw[];
    __nv_bfloat16* Hs = (__nv_bfloat16*)smem_raw;            // [BUF][NN]
    int*   n0_sh = (int*)(smem_raw + HBYTES);                // [RPB]
    int*   j0_sh = n0_sh + RPB;                              // [RPB*D0CAP]
    float* w0_sh = (float*)(j0_sh + RPB * D0CAP);            // [RPB*D0CAP]

    const int tid  = threadIdx.x;
    const int lane = tid & 31;
    const int wrp  = tid >> 5;
    const int i    = blockIdx.x * RPB + wrp;

    if (tid < RPB) n0_sh[tid] = 0;

    // stage full history into shared (vectorized, coalesced)
    {
        const uint4* src = (const uint4*)g_HT0;
        uint4* dst = (uint4*)Hs;
        for (int idx = tid; idx < HBYTES / 16; idx += THREADS)
            dst[idx] = src[idx];
    }
    __syncthreads();

    // step-invariant per-lane constants; compact d==0 entries into smem lists
    float wreg[KPL];
    int   dNN[KPL];                    // delay * NN (pre-scaled)
    const int f64 = g_flag64;
    const int* dp = (const int*)delays;
    #pragma unroll
    for (int k = 0; k < KPL; k++) {
        int j = lane + 32 * k;
        int e = i * NN + j;
        float w = fabsf(sc[e]);
        int d = f64 ? dp[2 * e] : dp[e];
        if (d == 0) {
            int p = atomicAdd(&n0_sh[wrp], 1);
            if (p < D0CAP) { j0_sh[wrp * D0CAP + p] = j; w0_sh[wrp * D0CAP + p] = w; }
            wreg[k] = 0.f;             // excluded from pre-gather
            dNN[k]  = NN;              // redirect to valid (never-racing) slot
        } else {
            wreg[k] = w;
            dNN[k]  = d * NN;
        }
    }
    __syncthreads();
    const int n0 = n0_sh[wrp];

    const float Gn  = 500.0f * g_invnorm;
    const float grs = Gn * g_rowsum[i];
    float x = hx[2 * i], y = hx[2 * i + 1];

    for (int t = 0; t < TT; t++) {
        // ---- prefetch step inputs (independent of barrier) ----
        float u = __ldg(&external[i * (SPT * TRS) + (t % SPT) * TRS + (t / SPT)]);
        float2 ns = *(const float2*)&noise[(size_t)t * 2 * NN + 2 * i];

        // ---- pre-gather: all d>=1 terms, from smem history (x <= t-2) ----
        const int base  = (t + BUF - 1) % BUF;       // slot of x(t-1)
        const int baseN = base * NN;
        float a0 = 0.f, a1 = 0.f;
        #pragma unroll
        for (int k = 0; k < KPL; k++) {
            int sN = baseN - dNN[k];
            if (sN < 0) sN += BUF * NN;
            float h = __bfloat162float(Hs[sN + lane + 32 * k]);
            if (k & 1) a1 = fmaf(wreg[k], h, a1);
            else       a0 = fmaf(wreg[k], h, a0);
        }
        float pre = warp_sum(a0 + a1);

        // ---- wait for x(t-1) from all blocks ----
        if (t) {
            if (tid == 0) {
                while (*((volatile int*)&g_go[t - 1]) == 0) { }
                __threadfence();
            }
            __syncthreads();
        }

        // ---- d==0 terms: read x(t-1) directly (critical path) ----
        const float* xprev = g_Xg + ((t - 1) & 1) * NN;
        float c0 = 0.f;
        if (t == 0) {
            for (int m = lane; m < n0; m += 32)
                c0 = fmaf(w0_sh[wrp * D0CAP + m],
                          __bfloat162float(Hs[baseN + j0_sh[wrp * D0CAP + m]]), c0);
        } else {
            for (int m = lane; m < n0; m += 32)
                c0 = fmaf(w0_sh[wrp * D0CAP + m],
                          __ldcg(xprev + j0_sh[wrp * D0CAP + m]), c0);
        }
        c0 = warp_sum(c0);

        // ---- append x(t-1) into history (off critical path, barrier shadow) ----
        if (t && tid < NN / 4) {
            float4 v = __ldcg((const float4*)xprev + tid);
            __nv_bfloat162* dr = (__nv_bfloat162*)(Hs + baseN);
            dr[2 * tid]     = __floats2bfloat162_rn(v.x, v.y);
            dr[2 * tid + 1] = __floats2bfloat162_rn(v.z, v.w);
        }

        // ---- Hopf update ----
        float LEd = pre + c0;
        float r2 = x * x + y * y;
        float dx = (-0.5f - r2) * x - 10.0f * y + Gn * LEd - grs * x + 5.0f * u;
        float dy = (-0.5f - r2) * y + 10.0f * x;
        x = x + 1e-4f * dx + ns.x;                  // sqrt(dt)*std_in = 1.0
        y = y + 1e-4f * dy + ns.y;

        if (lane == 0) {
            __stcg(&g_Xg[(t & 1) * NN + i], x);
            if (t % SPT == SPT - 1) g_XTR[(t / SPT) * NN + i] = x;
        }

        // ---- arrive: counter + release flag by last block ----
        __syncthreads();   // x stores + history append complete block-wide
        if (tid == 0) {
            __threadfence();
            int v = atomicAdd(&g_ctr[t], 1);
            if (v == NBLK - 1) {
                __threadfence();
                *((volatile int*)&g_go[t]) = 1;
            }
        }
    }
}

// ---------------- EEG projection: out[c][tr] = 5 * <x_tr, lm[c]> - 2 --------
__global__ void k_eeg(const float* __restrict__ lm, float* __restrict__ out) {
    int c = blockIdx.x, tr = blockIdx.y, tid = threadIdx.x;
    float s = 0.f;
    for (int i = tid; i < NN; i += 128)
        s += g_XTR[tr * NN + i] * lm[c * NN + i];
    #pragma unroll
    for (int o = 16; o; o >>= 1) s += __shfl_xor_sync(0xffffffffu, s, o);
    __shared__ float sh[4];
    if ((tid & 31) == 0) sh[tid >> 5] = s;
    __syncthreads();
    if (tid == 0) out[c * TRS + tr] = 5.0f * (sh[0] + sh[1] + sh[2] + sh[3]) - 2.0f;
}

extern "C" void kernel_launch(void* const* d_in, const int* in_sizes, int n_in,
                              void* d_out, int out_size) {
    const float* external = (const float*)d_in[0];
    const float* hx       = (const float*)d_in[1];
    const float* hE       = (const float*)d_in[2];
    const float* sc       = (const float*)d_in[3];
    const float* lm       = (const float*)d_in[4];
    const float* noise    = (const float*)d_in[5];
    const void*  delays   = d_in[6];

    const int smem = HBYTES + RPB * 4 + RPB * D0CAP * 8;
    cudaFuncSetAttribute(k_main, cudaFuncAttributeMaxDynamicSharedMemorySize, smem);

    k_rowstats<<<NN, 128>>>(sc);
    k_prep2<<<(BUF * NN + 255) / 256, 256>>>(hE, delays);
    k_norm<<<1, 256>>>();
    k_main<<<NBLK, THREADS, smem>>>(external, hx, sc, noise, delays);
    k_eeg<<<dim3(CC, TRS), 128>>>(lm, (float*)d_out);
}

// round 4
// speedup vs baseline: 1.5100x; 1.5100x over previous
#include <cuda_runtime.h>
#include <cuda_bf16.h>

#define NN   800
#define CC   64
#define TRS  40
#define SPT  10
#define BUF  120
#define TT   400
#define NBLK 100
#define RPB  8      // rows (warps) per block
#define THREADS 256
#define KPL  25     // 800 / 32 j-values per lane
#define D0CAP 96
#define HBYTES (BUF * NN * 2)

// ---------------- scratch (static device allocations; no cudaMalloc) --------
__device__ __align__(16) __nv_bfloat16 g_HT0[BUF * NN];  // transposed hE (bf16)
__device__ __align__(16) float g_XTR[TRS * NN];          // x at TR sample points
__device__ __align__(16) float g_Xg[2 * NN];             // ping-pong x(t) floats
__device__ int   g_ctr[TT];                              // per-step arrival counters
__device__ float g_rowsum[NN];
__device__ float g_rowsq[NN];
__device__ float g_invnorm;
__device__ int   g_flag64;

__device__ __forceinline__ int ld_cg32(const int* p) {
    int v;
    asm volatile("ld.global.cg.s32 %0, [%1];" : "=r"(v) : "l"(p) : "memory");
    return v;
}
__device__ __forceinline__ void red_add(int* p, int v) {
    asm volatile("red.global.add.s32 [%0], %1;" :: "l"(p), "r"(v) : "memory");
}

// ---------------- per-row stats --------------------------------------------
__global__ void k_rowstats(const float* __restrict__ sc) {
    int i = blockIdx.x, tid = threadIdx.x;
    float s1 = 0.f, s2 = 0.f;
    for (int j = tid; j < NN; j += 128) {
        float v = sc[i * NN + j];
        s1 += fabsf(v);
        s2 += v * v;
    }
    #pragma unroll
    for (int o = 16; o; o >>= 1) {
        s1 += __shfl_xor_sync(0xffffffffu, s1, o);
        s2 += __shfl_xor_sync(0xffffffffu, s2, o);
    }
    __shared__ float sh1[4], sh2[4];
    if ((tid & 31) == 0) { sh1[tid >> 5] = s1; sh2[tid >> 5] = s2; }
    __syncthreads();
    if (tid == 0) {
        g_rowsum[i] = sh1[0] + sh1[1] + sh1[2] + sh1[3];
        g_rowsq[i]  = sh2[0] + sh2[1] + sh2[2] + sh2[3];
    }
}

// ---------------- norm reduction -------------------------------------------
__global__ void k_norm() {
    int tid = threadIdx.x;
    float s = 0.f;
    for (int i = tid; i < NN; i += 256) s += g_rowsq[i];
    #pragma unroll
    for (int o = 16; o; o >>= 1) s += __shfl_xor_sync(0xffffffffu, s, o);
    __shared__ float sh[8];
    if ((tid & 31) == 0) sh[tid >> 5] = s;
    __syncthreads();
    if (tid == 0) {
        float tot = 0.f;
        #pragma unroll
        for (int w = 0; w < 8; w++) tot += sh[w];
        g_invnorm = rsqrtf(tot);
    }
}

// ---------------- prep: transpose hE -> bf16, reset counters, dtype detect --
__global__ void k_prep2(const float* __restrict__ hE, const void* __restrict__ delays) {
    int g = blockIdx.x * blockDim.x + threadIdx.x;
    if (g < BUF * NN) {
        int m = g / NN, j = g % NN;
        g_HT0[g] = __float2bfloat16(hE[j * BUF + (BUF - 1 - m)]);
    }
    if (g < TT) g_ctr[g] = 0;
    if (g == 0) {
        const int* p = (const int*)delays;
        int any = 0;
        for (int k = 0; k < 100; k++) any |= p[2 * k + 1];
        g_flag64 = (any == 0) ? 1 : 0;
    }
}

__device__ __forceinline__ float warp_sum(float v) {
    #pragma unroll
    for (int o = 16; o; o >>= 1) v += __shfl_xor_sync(0xffffffffu, v, o);
    return v;
}

// ---------------- main persistent integration kernel ------------------------
__global__ void __launch_bounds__(THREADS, 1)
k_main(const float* __restrict__ external, const float* __restrict__ hx,
       const float* __restrict__ sc, const float* __restrict__ noise,
       const void* __restrict__ delays) {
    extern __shared__ __align__(16) unsigned char smem_raw[];
    __nv_bfloat16* Hs = (__nv_bfloat16*)smem_raw;            // [BUF][NN]
    int*   n0_sh = (int*)(smem_raw + HBYTES);                // [RPB]
    int*   j0_sh = n0_sh + RPB;                              // [RPB*D0CAP]
    float* w0_sh = (float*)(j0_sh + RPB * D0CAP);            // [RPB*D0CAP]

    const int tid  = threadIdx.x;
    const int lane = tid & 31;
    const int wrp  = tid >> 5;
    const int i    = blockIdx.x * RPB + wrp;

    if (tid < RPB) n0_sh[tid] = 0;

    // stage full history into shared
    {
        const uint4* src = (const uint4*)g_HT0;
        uint4* dst = (uint4*)Hs;
        for (int idx = tid; idx < HBYTES / 16; idx += THREADS)
            dst[idx] = src[idx];
    }
    __syncthreads();

    // step-invariant constants; compact d==0 entries into smem lists
    float wreg[KPL];
    int   dNN[KPL];
    const int f64 = g_flag64;
    const int* dp = (const int*)delays;
    #pragma unroll
    for (int k = 0; k < KPL; k++) {
        int j = lane + 32 * k;
        int e = i * NN + j;
        float w = fabsf(sc[e]);
        int d = f64 ? dp[2 * e] : dp[e];
        if (d == 0) {
            int p = atomicAdd(&n0_sh[wrp], 1);
            if (p < D0CAP) { j0_sh[wrp * D0CAP + p] = j; w0_sh[wrp * D0CAP + p] = w; }
            wreg[k] = 0.f;
            dNN[k]  = NN;                 // harmless valid slot (weight is 0)
        } else {
            wreg[k] = w;
            dNN[k]  = d * NN;
        }
    }
    __syncthreads();
    const int n0 = n0_sh[wrp];

    const float Gn  = 500.0f * g_invnorm;
    const float grs = Gn * g_rowsum[i];
    float x = hx[2 * i], y = hx[2 * i + 1];

    for (int t = 0; t < TT; t++) {
        // ---- prefetch step inputs (issued before the wait; latency hidden) ----
        float u = __ldg(&external[i * (SPT * TRS) + (t % SPT) * TRS + (t / SPT)]);
        float2 ns = *(const float2*)&noise[(size_t)t * 2 * NN + 2 * i];

        const int baseN = ((t + BUF - 1) % BUF) * NN;   // slot of x(t-1)

        // ---- pre-gather: all d>=1 terms from smem (x <= t-2, already present) ----
        float a0 = 0.f, a1 = 0.f;
        #pragma unroll
        for (int k = 0; k < KPL; k++) {
            int sN = baseN - dNN[k];
            if (sN < 0) sN += BUF * NN;
            float h = __bfloat162float(Hs[sN + lane + 32 * k]);
            if (k & 1) a1 = fmaf(wreg[k], h, a1);
            else       a0 = fmaf(wreg[k], h, a0);
        }
        float pre = warp_sum(a0 + a1);

        // ---- wait for step t-1 completion: poll arrival counter directly ----
        if (t) {
            if (tid == 0) {
                while (ld_cg32(&g_ctr[t - 1]) < NBLK) { }
                __threadfence();   // acquire: x(t-1) stores now visible
            }
            __syncthreads();
        }

        // ---- d==0 terms: read x(t-1) floats (critical path) ----
        const float* xprev = g_Xg + ((t - 1) & 1) * NN;
        float c0 = 0.f;
        if (t == 0) {
            for (int m = lane; m < n0; m += 32)
                c0 = fmaf(w0_sh[wrp * D0CAP + m],
                          __bfloat162float(Hs[baseN + j0_sh[wrp * D0CAP + m]]), c0);
        } else {
            for (int m = lane; m < n0; m += 32)
                c0 = fmaf(w0_sh[wrp * D0CAP + m],
                          __ldcg(xprev + j0_sh[wrp * D0CAP + m]), c0);
        }
        c0 = warp_sum(c0);

        // ---- Hopf update ----
        float LEd = pre + c0;
        float r2 = x * x + y * y;
        float dx = (-0.5f - r2) * x - 10.0f * y + Gn * LEd - grs * x + 5.0f * u;
        float dy = (-0.5f - r2) * y + 10.0f * x;
        x = x + 1e-4f * dx + ns.x;
        y = y + 1e-4f * dy + ns.y;

        if (lane == 0) {
            __stcg(&g_Xg[(t & 1) * NN + i], x);
            if (t % SPT == SPT - 1) g_XTR[(t / SPT) * NN + i] = x;
        }

        // ---- append x(t-1) into smem history (off the serial chain) ----
        if (t && tid < NN / 4) {
            float4 v = __ldcg((const float4*)xprev + tid);
            __nv_bfloat162* dr = (__nv_bfloat162*)(Hs + baseN) + tid * 2;
            dr[0] = __floats2bfloat162_rn(v.x, v.y);
            dr[1] = __floats2bfloat162_rn(v.z, v.w);
        }

        // ---- arrive: all reads of x(t-1) and stores of x(t) complete ----
        __syncthreads();
        if (tid == 0) {
            __threadfence();               // release x(t) stores
            red_add(&g_ctr[t], 1);         // fire-and-forget arrival
        }
    }
}

// ---------------- EEG projection: out[c][tr] = 5 * <x_tr, lm[c]> - 2 --------
__global__ void k_eeg(const float* __restrict__ lm, float* __restrict__ out) {
    int c = blockIdx.x, tr = blockIdx.y, tid = threadIdx.x;
    float s = 0.f;
    for (int i = tid; i < NN; i += 128)
        s += g_XTR[tr * NN + i] * lm[c * NN + i];
    #pragma unroll
    for (int o = 16; o; o >>= 1) s += __shfl_xor_sync(0xffffffffu, s, o);
    __shared__ float sh[4];
    if ((tid & 31) == 0) sh[tid >> 5] = s;
    __syncthreads();
    if (tid == 0) out[c * TRS + tr] = 5.0f * (sh[0] + sh[1] + sh[2] + sh[3]) - 2.0f;
}

extern "C" void kernel_launch(void* const* d_in, const int* in_sizes, int n_in,
                              void* d_out, int out_size) {
    const float* external = (const float*)d_in[0];
    const float* hx       = (const float*)d_in[1];
    const float* hE       = (const float*)d_in[2];
    const float* sc       = (const float*)d_in[3];
    const float* lm       = (const float*)d_in[4];
    const float* noise    = (const float*)d_in[5];
    const void*  delays   = d_in[6];

    const int smem = HBYTES + RPB * 4 + RPB * D0CAP * 8;
    cudaFuncSetAttribute(k_main, cudaFuncAttributeMaxDynamicSharedMemorySize, smem);

    k_rowstats<<<NN, 128>>>(sc);
    k_prep2<<<(BUF * NN + 255) / 256, 256>>>(hE, delays);
    k_norm<<<1, 256>>>();
    k_main<<<NBLK, THREADS, smem>>>(external, hx, sc, noise, delays);
    k_eeg<<<dim3(CC, TRS), 128>>>(lm, (float*)d_out);
}